// round 7
// baseline (speedup 1.0000x reference)
#include <cuda_runtime.h>
#include <cstdint>

// CosineSim3D: out[b,n,:300] = softmax_n( (a_n . sum_m b_m/|b_m|) / |a_n| )
// B=128, N=M=1024, D=300. Single fused kernel, 1 block/batch, 1024 threads.
// Warp-private cp.async pipelines (depth 4, 1 row/stage): each lane copies and
// consumes the SAME float4 elements, so wait_group alone orders the data --
// zero block barriers inside the streaming loops. ~115KB in flight per SM.

static constexpr int BATCH   = 128;
static constexpr int NROW    = 1024;
static constexpr int DDIM    = 300;
static constexpr int NQ      = 75;      // float4 per row
static constexpr int DPAD    = 304;
static constexpr int THREADS = 1024;
static constexpr int WARPS   = 32;
static constexpr int TPW     = NROW / WARPS;   // 32 rows (time steps) per warp
static constexpr int D       = 4;              // pipeline depth (stages per warp)
static constexpr int ROW_F4  = 76;             // padded row: 76 float4 = 1216 B
static constexpr int ROW_B   = ROW_F4 * 16;

// dynamic smem layout (bytes)
static constexpr int RING_B    = WARPS * D * ROW_B;       // 155648
static constexpr int OFF_BSUM  = RING_B;                  // 304 floats
static constexpr int OFF_SCORE = OFF_BSUM + DPAD * 4;     // 1024 floats
static constexpr int OFF_RED   = OFF_SCORE + NROW * 4;    // 32 floats
static constexpr int SMEM_B    = OFF_RED + WARPS * 4;     // ~161 KB
// s_part (32 x 304 floats = 38912 B) overlays the ring between phases.

#define EPSV 1e-7f

__device__ __forceinline__ void cpa16(uint32_t dst_smem, const void* src) {
    asm volatile("cp.async.cg.shared.global [%0], [%1], 16;\n"
                 :: "r"(dst_smem), "l"(src));
}
__device__ __forceinline__ void cpa_commit() {
    asm volatile("cp.async.commit_group;\n");
}
template <int N>
__device__ __forceinline__ void cpa_wait() {
    asm volatile("cp.async.wait_group %0;\n" :: "n"(N));
}

__device__ __forceinline__ float warp_sum(float v) {
    #pragma unroll
    for (int o = 16; o > 0; o >>= 1) v += __shfl_xor_sync(0xffffffffu, v, o);
    return v;
}
__device__ __forceinline__ float warp_max(float v) {
    #pragma unroll
    for (int o = 16; o > 0; o >>= 1) v = fmaxf(v, __shfl_xor_sync(0xffffffffu, v, o));
    return v;
}
__device__ __forceinline__ float dot4(float4 x, float4 y) {
    return fmaf(x.x, y.x, fmaf(x.y, y.y, fmaf(x.z, y.z, x.w * y.w)));
}
__device__ __forceinline__ void axpy4(float4& acc, float4 q, float s) {
    acc.x = fmaf(q.x, s, acc.x);
    acc.y = fmaf(q.y, s, acc.y);
    acc.z = fmaf(q.z, s, acc.z);
    acc.w = fmaf(q.w, s, acc.w);
}

// one warp copies one row (this lane's own elements) into a ring stage
__device__ __forceinline__ void issue_row(uint32_t stage_u32, const float4* src,
                                          int lane, bool has_q2) {
    cpa16(stage_u32 + (uint32_t)lane * 16,        src + lane);
    cpa16(stage_u32 + (uint32_t)(lane + 32) * 16, src + lane + 32);
    if (has_q2)
        cpa16(stage_u32 + (uint32_t)(lane + 64) * 16, src + lane + 64);
}

__global__ void __launch_bounds__(THREADS, 1)
cosine_sim3d_kernel(const float* __restrict__ ga,
                    const float* __restrict__ gb,
                    float* __restrict__ gout)
{
    extern __shared__ __align__(16) char smem[];
    float* ring     = reinterpret_cast<float*>(smem);
    float* s_part   = reinterpret_cast<float*>(smem);             // overlays ring
    float* s_bsum   = reinterpret_cast<float*>(smem + OFF_BSUM);
    float* s_scores = reinterpret_cast<float*>(smem + OFF_SCORE);
    float* s_red    = reinterpret_cast<float*>(smem + OFF_RED);

    const int batch = blockIdx.x;
    const int tid   = threadIdx.x;
    const int wid   = tid >> 5;
    const int lane  = tid & 31;
    const bool has_q2 = lane < (NQ - 64);  // lane < 11
    const float4 f4z = make_float4(0.f, 0.f, 0.f, 0.f);

    const float4* a4 = reinterpret_cast<const float4*>(ga) + (size_t)batch * NROW * NQ;
    const float4* b4 = reinterpret_cast<const float4*>(gb) + (size_t)batch * NROW * NQ;
    float4*       o4 = reinterpret_cast<float4*>(gout)     + (size_t)batch * NROW * NQ;

    // this warp's ring stages (generic + shared-space addresses)
    const float4* my_ring4 = reinterpret_cast<const float4*>(ring) + (size_t)wid * D * ROW_F4;
    const uint32_t my_ring_u32 =
        (uint32_t)__cvta_generic_to_shared(ring) + (uint32_t)wid * D * ROW_B;

    // ================= Phase 1: bsum = sum_m b_m / ||b_m|| =================
    // warp w streams rows { t*32 + w : t in [0,32) } through its private ring
    float4 acc0 = f4z, acc1 = f4z, acc2 = f4z;

    #pragma unroll
    for (int s = 0; s < D - 1; s++) {
        issue_row(my_ring_u32 + s * ROW_B,
                  b4 + (size_t)(s * WARPS + wid) * NQ, lane, has_q2);
        cpa_commit();
    }

    #pragma unroll 1
    for (int t = 0; t < TPW; t++) {
        cpa_wait<D - 2>();

        const float4* r4 = my_ring4 + (t % D) * ROW_F4;
        float4 q0 = r4[lane];
        float4 q1 = r4[lane + 32];
        float4 q2 = has_q2 ? r4[lane + 64] : f4z;

        float ss = dot4(q0, q0) + dot4(q1, q1) + dot4(q2, q2);
        ss = warp_sum(ss);
        float inv = 1.0f / sqrtf(fmaxf(ss, EPSV));
        axpy4(acc0, q0, inv);
        axpy4(acc1, q1, inv);
        axpy4(acc2, q2, inv);

        const int tn = t + D - 1;
        if (tn < TPW)
            issue_row(my_ring_u32 + (tn % D) * ROW_B,
                      b4 + (size_t)(tn * WARPS + wid) * NQ, lane, has_q2);
        cpa_commit();   // uniform group accounting
    }
    cpa_wait<0>();
    __syncthreads();   // ring now reusable as s_part

    {
        float4* p4 = reinterpret_cast<float4*>(s_part + (size_t)wid * DPAD);
        p4[lane]      = acc0;
        p4[lane + 32] = acc1;
        if (has_q2) p4[lane + 64] = acc2;
    }
    __syncthreads();

    if (tid < DDIM) {
        float s = 0.f;
        #pragma unroll
        for (int w = 0; w < WARPS; w++) s += s_part[(size_t)w * DPAD + tid];
        s_bsum[tid] = s;
    }
    __syncthreads();   // s_part reads done; ring free for phase 2

    // ================= Phase 2: scores[n] = (a_n . bsum) / ||a_n|| =========
    float4 bs0, bs1, bs2;
    {
        const float4* bsum4 = reinterpret_cast<const float4*>(s_bsum);
        bs0 = bsum4[lane];
        bs1 = bsum4[lane + 32];
        bs2 = has_q2 ? bsum4[lane + 64] : f4z;
    }

    #pragma unroll
    for (int s = 0; s < D - 1; s++) {
        issue_row(my_ring_u32 + s * ROW_B,
                  a4 + (size_t)(s * WARPS + wid) * NQ, lane, has_q2);
        cpa_commit();
    }

    #pragma unroll 1
    for (int t = 0; t < TPW; t++) {
        cpa_wait<D - 2>();

        const float4* r4 = my_ring4 + (t % D) * ROW_F4;
        float4 q0 = r4[lane];
        float4 q1 = r4[lane + 32];
        float4 q2 = has_q2 ? r4[lane + 64] : f4z;

        float ss = dot4(q0, q0) + dot4(q1, q1) + dot4(q2, q2);
        float dt = dot4(q0, bs0) + dot4(q1, bs1) + dot4(q2, bs2);
        #pragma unroll
        for (int o = 16; o > 0; o >>= 1) {
            ss += __shfl_xor_sync(0xffffffffu, ss, o);
            dt += __shfl_xor_sync(0xffffffffu, dt, o);
        }
        if (lane == 0)
            s_scores[t * WARPS + wid] = dt / sqrtf(fmaxf(ss, EPSV));

        const int tn = t + D - 1;
        if (tn < TPW)
            issue_row(my_ring_u32 + (tn % D) * ROW_B,
                      a4 + (size_t)(tn * WARPS + wid) * NQ, lane, has_q2);
        cpa_commit();
    }
    cpa_wait<0>();
    __syncthreads();

    // ================= Phase 3: softmax over n =================
    float v0 = s_scores[tid];

    float mx = warp_max(v0);
    if (lane == 0) s_red[wid] = mx;
    __syncthreads();
    if (wid == 0) {
        float m = s_red[lane];           // WARPS == 32
        m = warp_max(m);
        if (lane == 0) s_red[0] = m;
    }
    __syncthreads();
    const float gmx = s_red[0];
    __syncthreads();

    float e0 = __expf(v0 - gmx);
    float sm = warp_sum(e0);
    if (lane == 0) s_red[wid] = sm;
    __syncthreads();
    if (wid == 0) {
        float s = s_red[lane];
        s = warp_sum(s);
        if (lane == 0) s_red[0] = s;
    }
    __syncthreads();
    const float inv_sum = 1.0f / s_red[0];

    s_scores[tid] = e0 * inv_sum;
    __syncthreads();

    // ================= Phase 4: tiled broadcast write =================
    const int rbase = wid * TPW;
    #pragma unroll 1
    for (int i = 0; i < TPW; i++) {
        const int row = rbase + i;
        const float p = s_scores[row];
        const float4 v = make_float4(p, p, p, p);
        float4* orow = o4 + (size_t)row * NQ;
        orow[lane]      = v;
        orow[lane + 32] = v;
        if (has_q2) orow[lane + 64] = v;
    }
}

extern "C" void kernel_launch(void* const* d_in, const int* in_sizes, int n_in,
                              void* d_out, int out_size) {
    const float* a = (const float*)d_in[0];
    const float* b = (const float*)d_in[1];
    float* out = (float*)d_out;
    static bool attr_set = false;
    if (!attr_set) {
        cudaFuncSetAttribute(cosine_sim3d_kernel,
                             cudaFuncAttributeMaxDynamicSharedMemorySize, SMEM_B);
        attr_set = true;
    }
    cosine_sim3d_kernel<<<BATCH, THREADS, SMEM_B>>>(a, b, out);
}

// round 8
// speedup vs baseline: 1.1589x; 1.1589x over previous
#include <cuda_runtime.h>
#include <cstdint>

// CosineSim3D: out[b,n,:300] = softmax_n( (a_n . sum_m b_m/|b_m|) / |a_n| )
// B=128, N=M=1024, D=300. Grid 256 = 2 half-blocks per batch (covers all 148
// SMs, all blocks co-resident) with self-cleaning atomic pair-rendezvous.

static constexpr int BATCH   = 128;
static constexpr int NROW    = 1024;
static constexpr int HROWS   = 512;            // rows per half-block
static constexpr int DDIM    = 300;
static constexpr int NQ      = 75;             // float4 per row
static constexpr int DPAD    = 304;
static constexpr int THREADS = 512;
static constexpr int WARPS   = 16;
static constexpr int RPW     = HROWS / WARPS;  // 32 rows per warp
static constexpr int RPI     = 2;
static constexpr int GRID    = BATCH * 2;      // 256 <= 148*2 resident slots

#define EPSV 1e-7f

// scratch + sync (zero-init at load; protocol restores zeros every run)
__device__ float g_part[BATCH][2][DPAD];
__device__ float g_scores[BATCH][NROW];
__device__ unsigned g_c[BATCH][2];   // arrive counters (rendezvous 0/1)
__device__ unsigned g_d[BATCH][2];   // passed counters

__device__ __forceinline__ float warp_sum(float v) {
    #pragma unroll
    for (int o = 16; o > 0; o >>= 1) v += __shfl_xor_sync(0xffffffffu, v, o);
    return v;
}
__device__ __forceinline__ float warp_max(float v) {
    #pragma unroll
    for (int o = 16; o > 0; o >>= 1) v = fmaxf(v, __shfl_xor_sync(0xffffffffu, v, o));
    return v;
}
__device__ __forceinline__ float dot4(float4 x, float4 y) {
    return fmaf(x.x, y.x, fmaf(x.y, y.y, fmaf(x.z, y.z, x.w * y.w)));
}
__device__ __forceinline__ void axpy4(float4& acc, float4 q, float s) {
    acc.x = fmaf(q.x, s, acc.x);
    acc.y = fmaf(q.y, s, acc.y);
    acc.z = fmaf(q.z, s, acc.z);
    acc.w = fmaf(q.w, s, acc.w);
}

// Pair rendezvous, graph-replay safe: arrive on c; spin to 2; count passers on
// d; the SECOND passer resets both to zero. Next replay sees zeros again.
// All threads fence before (publish) and thread0 fences after (acquire).
__device__ __forceinline__ void pair_rendezvous(unsigned* c, unsigned* d, int tid) {
    __threadfence();          // publish this thread's prior global writes
    __syncthreads();
    if (tid == 0) {
        atomicAdd(c, 1u);
        while (*(volatile unsigned*)c < 2u) __nanosleep(32);
        __threadfence();      // acquire partner's writes
        unsigned old = atomicAdd(d, 1u);
        if (old == 1u) {      // both passed the wait: safe to reset
            atomicExch(d, 0u);
            atomicExch(c, 0u);
        }
    }
    __syncthreads();
}

__global__ void __launch_bounds__(THREADS, 2)
cosine_sim3d_kernel(const float* __restrict__ ga,
                    const float* __restrict__ gb,
                    float* __restrict__ gout)
{
    __shared__ __align__(16) float s_part[WARPS][DPAD];  // 19.5 KB
    __shared__ __align__(16) float s_bsum[DPAD];
    __shared__ float s_sc[HROWS];                        // own half's raw scores
    __shared__ float s_red[WARPS];

    const int batch = blockIdx.x >> 1;
    const int half  = blockIdx.x & 1;
    const int tid   = threadIdx.x;
    const int wid   = tid >> 5;
    const int lane  = tid & 31;
    const bool has_q2 = lane < (NQ - 64);  // lane < 11
    const float4 f4z = make_float4(0.f, 0.f, 0.f, 0.f);

    const float4* a4 = reinterpret_cast<const float4*>(ga) + (size_t)batch * NROW * NQ;
    const float4* b4 = reinterpret_cast<const float4*>(gb) + (size_t)batch * NROW * NQ;
    float4*       o4 = reinterpret_cast<float4*>(gout)     + (size_t)batch * NROW * NQ;

    const int rbase = half * HROWS + wid * RPW;   // first global row for this warp

    // ========== Phase 1: partial bsum over this half's 512 b-rows ==========
    float4 acc0 = f4z, acc1 = f4z, acc2 = f4z;

    #pragma unroll 1
    for (int i = 0; i < RPW; i += RPI) {
        float4 q0[RPI], q1[RPI], q2[RPI];
        #pragma unroll
        for (int r = 0; r < RPI; r++) {
            const float4* row = b4 + (size_t)(rbase + i + r) * NQ;
            q0[r] = __ldcs(row + lane);
            q1[r] = __ldcs(row + lane + 32);
            q2[r] = has_q2 ? __ldcs(row + lane + 64) : f4z;
        }
        #pragma unroll
        for (int r = 0; r < RPI; r++) {
            float ss = dot4(q0[r], q0[r]) + dot4(q1[r], q1[r]) + dot4(q2[r], q2[r]);
            ss = warp_sum(ss);
            float inv = 1.0f / sqrtf(fmaxf(ss, EPSV));
            axpy4(acc0, q0[r], inv);
            axpy4(acc1, q1[r], inv);
            axpy4(acc2, q2[r], inv);
        }
    }

    {
        float4* p4 = reinterpret_cast<float4*>(&s_part[wid][0]);
        p4[lane]      = acc0;
        p4[lane + 32] = acc1;
        if (has_q2) p4[lane + 64] = acc2;
    }
    __syncthreads();

    if (tid < DDIM) {
        float s = 0.f;
        #pragma unroll
        for (int w = 0; w < WARPS; w++) s += s_part[w][tid];
        g_part[batch][half][tid] = s;
    }

    // ========== Rendezvous 1: both halves' partials ready ==========
    pair_rendezvous(&g_c[batch][0], &g_d[batch][0], tid);

    if (tid < DDIM)
        s_bsum[tid] = __ldcg(&g_part[batch][0][tid]) + __ldcg(&g_part[batch][1][tid]);
    __syncthreads();

    float4 bs0, bs1, bs2;
    {
        const float4* bsum4 = reinterpret_cast<const float4*>(s_bsum);
        bs0 = bsum4[lane];
        bs1 = bsum4[lane + 32];
        bs2 = has_q2 ? bsum4[lane + 64] : f4z;
    }

    // ========== Phase 2: scores for this half's 512 a-rows ==========
    #pragma unroll 1
    for (int i = 0; i < RPW; i += RPI) {
        float4 q0[RPI], q1[RPI], q2[RPI];
        #pragma unroll
        for (int r = 0; r < RPI; r++) {
            const float4* row = a4 + (size_t)(rbase + i + r) * NQ;
            q0[r] = __ldcs(row + lane);
            q1[r] = __ldcs(row + lane + 32);
            q2[r] = has_q2 ? __ldcs(row + lane + 64) : f4z;
        }
        #pragma unroll
        for (int r = 0; r < RPI; r++) {
            float ss = dot4(q0[r], q0[r]) + dot4(q1[r], q1[r]) + dot4(q2[r], q2[r]);
            float dt = dot4(q0[r], bs0) + dot4(q1[r], bs1) + dot4(q2[r], bs2);
            #pragma unroll
            for (int o = 16; o > 0; o >>= 1) {
                ss += __shfl_xor_sync(0xffffffffu, ss, o);
                dt += __shfl_xor_sync(0xffffffffu, dt, o);
            }
            if (lane == 0)
                g_scores[batch][rbase + i + r] = dt / sqrtf(fmaxf(ss, EPSV));
        }
    }

    // ========== Rendezvous 2: all 1024 scores ready ==========
    pair_rendezvous(&g_c[batch][1], &g_d[batch][1], tid);

    // ========== Phase 3: softmax stats (redundant in both halves) ==========
    // own-half score -> smem for the write phase; other half only for stats.
    const float v_own = __ldcg(&g_scores[batch][half * HROWS + tid]);
    const float v_oth = __ldcg(&g_scores[batch][(1 - half) * HROWS + tid]);
    s_sc[tid] = v_own;

    float mx = warp_max(fmaxf(v_own, v_oth));
    if (lane == 0) s_red[wid] = mx;
    __syncthreads();
    if (wid == 0) {
        float m = (lane < WARPS) ? s_red[lane] : -3.4e38f;
        m = warp_max(m);
        if (lane == 0) s_red[0] = m;
    }
    __syncthreads();
    const float gmx = s_red[0];
    __syncthreads();

    // e(own)+e(oth): same operand pair in both halves -> commutative add ->
    // bitwise-identical partials -> identical block sum in both halves.
    float es = __expf(v_own - gmx) + __expf(v_oth - gmx);
    es = warp_sum(es);
    if (lane == 0) s_red[wid] = es;
    __syncthreads();
    if (wid == 0) {
        float s = (lane < WARPS) ? s_red[lane] : 0.f;
        s = warp_sum(s);
        if (lane == 0) s_red[0] = s;
    }
    __syncthreads();
    const float inv_sum = 1.0f / s_red[0];

    // ========== Phase 4: broadcast-write this half's 512 rows ==========
    const int lbase = wid * RPW;   // local row base within the half
    #pragma unroll 1
    for (int i = 0; i < RPW; i++) {
        const float p = __expf(s_sc[lbase + i] - gmx) * inv_sum;
        const float4 pv = make_float4(p, p, p, p);
        float4* orow = o4 + (size_t)(half * HROWS + lbase + i) * NQ;
        orow[lane]      = pv;
        orow[lane + 32] = pv;
        if (has_q2) orow[lane + 64] = pv;
    }
}

extern "C" void kernel_launch(void* const* d_in, const int* in_sizes, int n_in,
                              void* d_out, int out_size) {
    const float* a = (const float*)d_in[0];
    const float* b = (const float*)d_in[1];
    float* out = (float*)d_out;
    cosine_sim3d_kernel<<<GRID, THREADS>>>(a, b, out);
}